// round 13
// baseline (speedup 1.0000x reference)
#include <cuda_runtime.h>
#include <cuda_bf16.h>
#include <cstdint>

// ---------------------------------------------------------------------------
// TimemixingFC_channel, round 13: 2-D warp tiling (32 rows x 48 cols) to cut
// duplicated B-weight LDS traffic (-29% L1 bytes), after R12 falsified the
// ILP-starvation theory (mega-phase gained ~0).
//   Algebra: per branch qkv = x@W^T + b; S=2 attention -> 2x2 G per
//   (position, window) group; o = q@G; proj. Branch-0 proj folded into
//   branch-1 qkv (W' = Wsw@Wp, b' = Wsw@bp + bsw). Rolls folded into pairing.
//   Warp layout: 8 warps = 4 row-slabs(32) x 2 col-halves(48). A fragments
//   cached (48 regs) across K/V/Q. G per col-half -> gt2[row][half] -> gc.
//   Phases: stage(K,V,A) -> KV loop (fold G) -> restage(Q,proj) -> G reduce
//   -> Q+o -> [proj]. 73.7KB smem, grid 256 x 256thr.
// ---------------------------------------------------------------------------

#define SMEM_BYTES 73728

static __device__ __align__(16) __nv_bfloat16 g_mid[32768 * 96];   // o0 (bf16)
static __device__ __align__(16) __nv_bfloat16 g_wbf[2][288 * 104]; // qkv W, [jf][c] pad104
static __device__ __align__(16) __nv_bfloat16 g_wpbf[96 * 104];    // projs_w
static __device__ float g_b1[288];                                 // b' fold bias

// ---- PTX helpers (valid under compute_100) --------------------------------
__device__ __forceinline__ uint32_t smem_u32(const void* p) {
    uint32_t a;
    asm("{ .reg .u64 t; cvta.to.shared.u64 t, %1; cvt.u32.u64 %0, t; }" : "=r"(a) : "l"(p));
    return a;
}
#define CPA16(dst, src) \
    asm volatile("cp.async.cg.shared.global [%0], [%1], 16;" :: "r"(dst), "l"(src) : "memory")
#define CPA_COMMIT() asm volatile("cp.async.commit_group;" ::: "memory")
#define CPA_WAIT(n)  asm volatile("cp.async.wait_group %0;" :: "n"(n) : "memory")

__device__ __forceinline__ void ldsm4(uint32_t& r0, uint32_t& r1, uint32_t& r2,
                                      uint32_t& r3, uint32_t addr) {
    asm volatile("ldmatrix.sync.aligned.m8n8.x4.shared.b16 {%0,%1,%2,%3}, [%4];"
                 : "=r"(r0), "=r"(r1), "=r"(r2), "=r"(r3) : "r"(addr));
}
#define MMA(acc, a, b0, b1) \
    asm volatile("mma.sync.aligned.m16n8k16.row.col.f32.bf16.bf16.f32 " \
        "{%0,%1,%2,%3}, {%4,%5,%6,%7}, {%8,%9}, {%0,%1,%2,%3};" \
        : "+f"((acc)[0]), "+f"((acc)[1]), "+f"((acc)[2]), "+f"((acc)[3]) \
        : "r"((a)[0]), "r"((a)[1]), "r"((a)[2]), "r"((a)[3]), "r"(b0), "r"(b1))

// ---------------------------------------------------------------------------
// Prep 1: bf16 transposes only (no smem). Grid 144 x 256.
// ---------------------------------------------------------------------------
__global__ void prep_tr(const float* __restrict__ lr,
                        const float* __restrict__ prs)
{
    int idx = blockIdx.x * 256 + threadIdx.x;   // < 36864
    if (idx < 27648) {
        int jf = idx / 96, c = idx % 96;
        g_wbf[0][jf * 104 + c] = __float2bfloat16(lr[idx]);
    } else {
        int i2 = idx - 27648;
        int j = i2 / 96, c = i2 % 96;
        g_wpbf[j * 104 + c] = __float2bfloat16(prs[i2]);
    }
}

// ---------------------------------------------------------------------------
// Prep 2: W' = sw_w @ proj_w -> g_wbf[1]; b' = sw_w @ proj_b + sw_b -> g_b1.
// Grid 19 x 256 (R11-proven).
// ---------------------------------------------------------------------------
__global__ void prep_fold(const float* __restrict__ pr,
                          const float* __restrict__ sw,
                          const float* __restrict__ swb,
                          const float* __restrict__ prb)
{
    __shared__ float prs_s[96 * 100];
    __shared__ float sws[16 * 96];
    int bid = blockIdx.x, tid = threadIdx.x;

    if (bid < 18) {
        int jf0 = bid * 16;
        for (int i = tid; i < 2304; i += 256) {
            int t = i / 24, c4 = (i % 24) * 4;
            *(float4*)&prs_s[t * 100 + c4] = *(const float4*)&pr[t * 96 + c4];
        }
        for (int i = tid; i < 1536; i += 256)
            sws[i] = sw[jf0 * 96 + i];
        __syncthreads();

        int rgrp = tid >> 4, cgrp = tid & 15;
        int c0 = cgrp * 6;
        const float* swr = &sws[rgrp * 96];
        float acc[6];
#pragma unroll
        for (int j = 0; j < 6; j++) acc[j] = 0.f;
#pragma unroll 4
        for (int t = 0; t < 96; t++) {
            float s = swr[t];
#pragma unroll
            for (int j = 0; j < 6; j++)
                acc[j] = fmaf(s, prs_s[t * 100 + c0 + j], acc[j]);
        }
        int jf = jf0 + rgrp;
#pragma unroll
        for (int j = 0; j < 6; j++)
            g_wbf[1][jf * 104 + c0 + j] = __float2bfloat16(acc[j]);
    } else {
        if (tid < 96) sws[tid] = prb[tid];
        __syncthreads();
        int rgrp = tid >> 4, cgrp = tid & 15;
        int c0 = cgrp * 6;
        for (int r = rgrp; r < 288; r += 16) {
            const float* swr = sw + r * 96;
            float pacc = 0.f;
#pragma unroll
            for (int t = 0; t < 6; t++)
                pacc = fmaf(swr[c0 + t], sws[c0 + t], pacc);
#pragma unroll
            for (int off = 1; off < 16; off <<= 1)
                pacc += __shfl_xor_sync(0xffffffffu, pacc, off);
            if (cgrp == 0) g_b1[r] = pacc + swb[r];
        }
    }
}

// ---------------------------------------------------------------------------
// Quad MMA: 2 m-slabs x 2 n-tiles for n-tile-pair p, K=96, cached A frags.
// B loaded once, reused by both m-slabs (the traffic win).
// ---------------------------------------------------------------------------
__device__ __forceinline__ void hmma_quad(const uint32_t af0[6][4],
                                          const uint32_t af1[6][4],
                                          uint32_t wAddr, int p,
                                          float acc[2][2][4])
{
#pragma unroll
    for (int m = 0; m < 2; m++)
#pragma unroll
        for (int t = 0; t < 2; t++)
#pragma unroll
            for (int r = 0; r < 4; r++) acc[m][t][r] = 0.f;
#pragma unroll
    for (int ks = 0; ks < 6; ks++) {
        uint32_t b0, b1, b2, b3;
        ldsm4(b0, b1, b2, b3, wAddr + p * 3328 + ks * 32);
        MMA(acc[0][0], af0[ks], b0, b2);
        MMA(acc[0][1], af0[ks], b1, b3);
        MMA(acc[1][0], af1[ks], b0, b2);
        MMA(acc[1][1], af1[ks], b1, b3);
    }
}

// stage one 96x104-bf16 weight image (19968B = 1248 x 16B) via cp.async
__device__ __forceinline__ void stage_w_async(uint32_t dst, const char* src, int tid)
{
    for (int f = tid; f < 1248; f += 256)
        CPA16(dst + f * 16, src + f * 16);
}

// ---------------------------------------------------------------------------
// Fused branch. Grid 256 x 256. Block = 64 position-groups x 2 frames.
// smem: tb 512 | qb 1152 | pb 384 | gt2 4096 | gc 1024 | A 26624 | W x2 39936
// ---------------------------------------------------------------------------
__global__ void __launch_bounds__(256, 2)
fused_branch(const float* __restrict__ xin_ext,
             const float* __restrict__ qkv_b_ext,
             const float* __restrict__ pr_b,
             float* __restrict__ out_ext,
             int branch, int shift)
{
    extern __shared__ char smem[];
    int*   tb  = (int*)smem;                 // 128 token bases
    float* qb  = (float*)(smem + 512);       // 288 qkv biases
    float* pb  = (float*)(smem + 1664);      // 96 proj biases
    float* gt2 = (float*)(smem + 2048);      // [128 rows][2 halves][4]
    float* gc  = (float*)(smem + 6144);      // [64 groups][4]
    char*  smA = smem + 7168;                // [128][104] bf16 (x / o tile)

    uint32_t sb   = smem_u32(smem);
    uint32_t smAu = sb + 7168;
    uint32_t smWu = sb + 33792;              // 2 x [96][104] bf16 slots

    int tid = threadIdx.x, w = tid >> 5, lane = tid & 31;
    int g = lane >> 2, tig = lane & 3;
    int l16 = lane & 15, lh = lane >> 4;
    int slab = w >> 1, half = w & 1;
    int row0 = slab * 32;
    int jbase = half * 48;

    const float* QB = branch ? g_b1 : qkv_b_ext;
    for (int i = tid; i < 288; i += 256) qb[i] = QB[i];
    if (branch && tid < 96) pb[tid] = pr_b[tid];

    if (tid < 128) {
        int pi = tid & 63;
        int gg = (blockIdx.x << 6) + pi;
        int b = gg >> 13, dw = (gg >> 10) & 7, p = gg & 1023;
        int d = (2 * dw + (tid >> 6) + shift) & 15;
        tb[tid] = ((b * 16 + d) * 1024 + p) * 96;
    }

    const char* WB = (const char*)g_wbf[branch];

    if (branch == 0) {
        stage_w_async(smWu,         WB + 96 * 208, tid);  // K -> slot0
        stage_w_async(smWu + 19968, WB + 192 * 208, tid); // V -> slot1
        CPA_COMMIT();
        __syncthreads();   // tb ready
        for (int f4 = tid; f4 < 3072; f4 += 256) {
            int l = f4 / 24, q4 = f4 % 24;
            float4 v = *(const float4*)&xin_ext[tb[l] + q4 * 4];
            __nv_bfloat162 p0 = __floats2bfloat162_rn(v.x, v.y);
            __nv_bfloat162 p1 = __floats2bfloat162_rn(v.z, v.w);
            *(uint2*)(smA + l * 208 + q4 * 8) =
                make_uint2(*(uint32_t*)&p0, *(uint32_t*)&p1);
        }
    } else {
        __syncthreads();   // tb ready
        for (int f = tid; f < 1536; f += 256) {       // A tile via cp.async
            int l = f / 12, u = f % 12;
            CPA16(smAu + l * 208 + u * 16,
                  (const char*)g_mid + (size_t)tb[l] * 2 + u * 16);
        }
        stage_w_async(smWu,         WB + 96 * 208, tid);  // K
        stage_w_async(smWu + 19968, WB + 192 * 208, tid); // V
        CPA_COMMIT();
    }

    uint32_t aAddr0 = smAu + ((row0 + l16) * 104 + lh * 8) * 2;
    uint32_t aAddr1 = smAu + ((row0 + 16 + l16) * 104 + lh * 8) * 2;
    uint32_t wAddr  = smWu + ((jbase + l16) * 104 + lh * 8) * 2;

    CPA_WAIT(0);
    __syncthreads();        // A + K + V visible

    // ---- cache A fragments for both m-slabs (reused by K, V, Q) ----
    uint32_t af0[6][4], af1[6][4];
#pragma unroll
    for (int ks = 0; ks < 6; ks++) {
        ldsm4(af0[ks][0], af0[ks][1], af0[ks][2], af0[ks][3], aAddr0 + ks * 32);
        ldsm4(af1[ks][0], af1[ks][1], af1[ks][2], af1[ks][3], aAddr1 + ks * 32);
    }

    // ---- K/V per n-tile pair (this warp's 48 cols), fold into G ----
    float G[2][8];          // [m-slab][row g: 00,01,10,11 | row g+8: ...]
#pragma unroll
    for (int m = 0; m < 2; m++)
#pragma unroll
        for (int i = 0; i < 8; i++) G[m][i] = 0.f;
#pragma unroll
    for (int p = 0; p < 3; p++) {
        float ka[2][2][4], va[2][2][4];
        hmma_quad(af0, af1, wAddr,         p, ka);
        hmma_quad(af0, af1, wAddr + 19968, p, va);
#pragma unroll
        for (int t = 0; t < 2; t++) {
            int j0 = jbase + p * 16 + t * 8 + tig * 2;
            float kb0 = qb[96 + j0], kb1 = qb[96 + j0 + 1];
            float vb0 = qb[192 + j0], vb1 = qb[192 + j0 + 1];
#pragma unroll
            for (int m = 0; m < 2; m++) {
                float k0 = ka[m][t][0] + kb0, k1 = ka[m][t][1] + kb1;
                float k2 = ka[m][t][2] + kb0, k3 = ka[m][t][3] + kb1;
                float v0 = va[m][t][0] + vb0, v1 = va[m][t][1] + vb1;
                float v2 = va[m][t][2] + vb0, v3 = va[m][t][3] + vb1;
                G[m][0] = fmaf(k0, v0, G[m][0]); G[m][1] = fmaf(k0, v1, G[m][1]);
                G[m][2] = fmaf(k1, v0, G[m][2]); G[m][3] = fmaf(k1, v1, G[m][3]);
                G[m][4] = fmaf(k2, v2, G[m][4]); G[m][5] = fmaf(k2, v3, G[m][5]);
                G[m][6] = fmaf(k3, v2, G[m][6]); G[m][7] = fmaf(k3, v3, G[m][7]);
            }
        }
    }
    __syncthreads();        // all warps done with K/V weight slots

    // re-stage slot0 = Q weights, slot1 = proj weights (branch1)
    stage_w_async(smWu, WB, tid);
    if (branch) stage_w_async(smWu + 19968, (const char*)g_wpbf, tid);
    CPA_COMMIT();

    // ---- reduce G over the 4 tig lanes; write per-(row, col-half) ----
#pragma unroll
    for (int off = 1; off <= 2; off <<= 1)
#pragma unroll
        for (int m = 0; m < 2; m++)
#pragma unroll
            for (int i = 0; i < 8; i++)
                G[m][i] += __shfl_xor_sync(0xffffffffu, G[m][i], off);
    if (tig == 0) {
#pragma unroll
        for (int m = 0; m < 2; m++) {
            int r = row0 + m * 16 + g;
            *(float4*)&gt2[(r * 2 + half) * 4] =
                make_float4(G[m][0], G[m][1], G[m][2], G[m][3]);
            *(float4*)&gt2[((r + 8) * 2 + half) * 4] =
                make_float4(G[m][4], G[m][5], G[m][6], G[m][7]);
        }
    }
    __syncthreads();
    if (tid < 64) {
        float4 a0 = *(float4*)&gt2[(tid * 2) * 4];
        float4 a1 = *(float4*)&gt2[(tid * 2 + 1) * 4];
        float4 b0 = *(float4*)&gt2[((tid + 64) * 2) * 4];
        float4 b1 = *(float4*)&gt2[((tid + 64) * 2 + 1) * 4];
        *(float4*)&gc[tid * 4] = make_float4(a0.x + a1.x + b0.x + b1.x,
                                             a0.y + a1.y + b0.y + b1.y,
                                             a0.z + a1.z + b0.z + b1.z,
                                             a0.w + a1.w + b0.w + b1.w);
    }
    CPA_WAIT(0);
    __syncthreads();        // gc + Q (+proj) weights visible

    // per-thread G for its 4 rows
    float4 Gr[2][2];
#pragma unroll
    for (int m = 0; m < 2; m++) {
        Gr[m][0] = *(float4*)&gc[((row0 + m * 16 + g) & 63) * 4];
        Gr[m][1] = *(float4*)&gc[((row0 + m * 16 + g + 8) & 63) * 4];
    }

    // ---- Q per pair + o = q @ G -> bf16 into smA ----
#pragma unroll
    for (int p = 0; p < 3; p++) {
        float qa[2][2][4];
        hmma_quad(af0, af1, wAddr, p, qa);   // slot0 = Q weights
#pragma unroll
        for (int t = 0; t < 2; t++) {
            int j0 = jbase + p * 16 + t * 8 + tig * 2;
            float b0 = qb[j0], b1 = qb[j0 + 1];
#pragma unroll
            for (int m = 0; m < 2; m++) {
                float q0 = qa[m][t][0] + b0, q1 = qa[m][t][1] + b1;
                float q2 = qa[m][t][2] + b0, q3 = qa[m][t][3] + b1;
                float o0 = q0 * Gr[m][0].x + q1 * Gr[m][0].z;
                float o1 = q0 * Gr[m][0].y + q1 * Gr[m][0].w;
                float o2 = q2 * Gr[m][1].x + q3 * Gr[m][1].z;
                float o3 = q2 * Gr[m][1].y + q3 * Gr[m][1].w;
                __nv_bfloat162 plo = __floats2bfloat162_rn(o0, o1);
                __nv_bfloat162 phi = __floats2bfloat162_rn(o2, o3);
                int r = row0 + m * 16 + g;
                *(uint32_t*)(smA + r * 208 + j0 * 2)       = *(uint32_t*)&plo;
                *(uint32_t*)(smA + (r + 8) * 208 + j0 * 2) = *(uint32_t*)&phi;
            }
        }
    }

    if (branch == 0) {
        // ---- o tile -> g_mid (coalesced uint4 rows) ----
        __syncthreads();
        for (int f = tid; f < 1536; f += 256) {
            int l = f / 12, u = f % 12;
            *(uint4*)((char*)g_mid + (size_t)tb[l] * 2 + u * 16) =
                *(const uint4*)(smA + l * 208 + u * 16);
        }
    } else {
        // ---- proj: o tile @ projs_w^T + pb -> out ----
        __syncthreads();    // o cols from both halves must be visible
#pragma unroll
        for (int ks = 0; ks < 6; ks++) {
            ldsm4(af0[ks][0], af0[ks][1], af0[ks][2], af0[ks][3], aAddr0 + ks * 32);
            ldsm4(af1[ks][0], af1[ks][1], af1[ks][2], af1[ks][3], aAddr1 + ks * 32);
        }
        int tbr[2][2];
#pragma unroll
        for (int m = 0; m < 2; m++) {
            tbr[m][0] = tb[row0 + m * 16 + g];
            tbr[m][1] = tb[row0 + m * 16 + g + 8];
        }
#pragma unroll
        for (int p = 0; p < 3; p++) {
            float pa[2][2][4];
            hmma_quad(af0, af1, wAddr + 19968, p, pa);   // slot1 = proj
#pragma unroll
            for (int t = 0; t < 2; t++) {
                int j0 = jbase + p * 16 + t * 8 + tig * 2;
                float b0 = pb[j0], b1 = pb[j0 + 1];
#pragma unroll
                for (int m = 0; m < 2; m++) {
                    *(float2*)&out_ext[tbr[m][0] + j0] =
                        make_float2(pa[m][t][0] + b0, pa[m][t][1] + b1);
                    *(float2*)&out_ext[tbr[m][1] + j0] =
                        make_float2(pa[m][t][2] + b0, pa[m][t][3] + b1);
                }
            }
        }
    }
}

// ---------------------------------------------------------------------------
extern "C" void kernel_launch(void* const* d_in, const int* in_sizes, int n_in,
                              void* d_out, int out_size)
{
    const float* x       = (const float*)d_in[0];
    const float* lr_w    = (const float*)d_in[1];
    const float* lr_b    = (const float*)d_in[2];
    const float* proj_w  = (const float*)d_in[3];
    const float* proj_b  = (const float*)d_in[4];
    const float* sw_w    = (const float*)d_in[5];
    const float* sw_b    = (const float*)d_in[6];
    const float* projs_w = (const float*)d_in[7];
    const float* projs_b = (const float*)d_in[8];
    float* out = (float*)d_out;

    cudaFuncSetAttribute(fused_branch,
                         cudaFuncAttributeMaxDynamicSharedMemorySize, SMEM_BYTES);

    prep_tr<<<144, 256>>>(lr_w, projs_w);
    prep_fold<<<19, 256>>>(proj_w, sw_w, sw_b, proj_b);
    // branch 0: pairs (2w, 2w+1), x -> o0 (g_mid bf16); proj folded forward
    fused_branch<<<256, 256, SMEM_BYTES>>>(x, lr_b, nullptr, nullptr, 0, 0);
    // branch 1: pairs ((2w+15)&15, 2w); qkv' on o0, projs -> out
    fused_branch<<<256, 256, SMEM_BYTES>>>(nullptr, nullptr, projs_b, out, 1, 15);
}

// round 14
// speedup vs baseline: 1.2813x; 1.2813x over previous
#include <cuda_runtime.h>
#include <cuda_bf16.h>
#include <cstdint>

// ---------------------------------------------------------------------------
// TimemixingFC_channel, round 14: single mega-kernel, local producer/consumer
// sync. R12/R13 falsified ILP- and L1-traffic-bound theories (dur pinned at
// ~17.7us/launch); remaining serial structure = 3 launches + a global barrier
// where the true dep is local: branch1 block (b,dw,chunk) needs only branch0
// blocks (b,dw,chunk)[self] and (b,dw-1,chunk).
//   Grid 278 = 256 work + 18 W'-fold + 1 b' + 3 projs-transpose blocks, all
//   resident in wave 1 (<=296 slots) -> deadlock-free. Work block: phaseA
//   (R12 branch0 body) -> fence+flag -> spin(1 flag + fold counter) ->
//   phaseB (R12 branch1 body). Side blocks hide under phaseA (~20us).
//   prep_tr = lr transpose + flag zeroing (graph-replay safe).
// ---------------------------------------------------------------------------

#define SMEM_BYTES 91648

static __device__ __align__(16) __nv_bfloat16 g_mid[32768 * 96];   // o0 (bf16)
static __device__ __align__(16) __nv_bfloat16 g_wbf[2][288 * 104]; // qkv W, [jf][c] pad104
static __device__ __align__(16) __nv_bfloat16 g_wpbf[96 * 104];    // projs_w
static __device__ float g_b1[288];                                 // b' fold bias
static __device__ int   g_flag[256];                               // phaseA done flags
static __device__ int   g_fold;                                    // side-block counter

// ---- PTX helpers (valid under compute_100) --------------------------------
__device__ __forceinline__ uint32_t smem_u32(const void* p) {
    uint32_t a;
    asm("{ .reg .u64 t; cvta.to.shared.u64 t, %1; cvt.u32.u64 %0, t; }" : "=r"(a) : "l"(p));
    return a;
}
#define CPA16(dst, src) \
    asm volatile("cp.async.cg.shared.global [%0], [%1], 16;" :: "r"(dst), "l"(src) : "memory")
#define CPA_COMMIT() asm volatile("cp.async.commit_group;" ::: "memory")
#define CPA_WAIT(n)  asm volatile("cp.async.wait_group %0;" :: "n"(n) : "memory")

__device__ __forceinline__ void ldsm4(uint32_t& r0, uint32_t& r1, uint32_t& r2,
                                      uint32_t& r3, uint32_t addr) {
    asm volatile("ldmatrix.sync.aligned.m8n8.x4.shared.b16 {%0,%1,%2,%3}, [%4];"
                 : "=r"(r0), "=r"(r1), "=r"(r2), "=r"(r3) : "r"(addr));
}
#define MMA(acc, a, b0, b1) \
    asm volatile("mma.sync.aligned.m16n8k16.row.col.f32.bf16.bf16.f32 " \
        "{%0,%1,%2,%3}, {%4,%5,%6,%7}, {%8,%9}, {%0,%1,%2,%3};" \
        : "+f"((acc)[0]), "+f"((acc)[1]), "+f"((acc)[2]), "+f"((acc)[3]) \
        : "r"((a)[0]), "r"((a)[1]), "r"((a)[2]), "r"((a)[3]), "r"(b0), "r"(b1))

// ---------------------------------------------------------------------------
// Prep: lr transpose + flag zeroing. Grid 108 x 256 (27648 = 108*256).
// ---------------------------------------------------------------------------
__global__ void prep_tr(const float* __restrict__ lr)
{
    int idx = blockIdx.x * 256 + threadIdx.x;
    int jf = idx / 96, c = idx % 96;
    g_wbf[0][jf * 104 + c] = __float2bfloat16(lr[idx]);
    if (blockIdx.x == 0) {
        g_flag[threadIdx.x] = 0;
        if (threadIdx.x == 0) g_fold = 0;
    }
}

// ---------------------------------------------------------------------------
// One n-tile pair (tiles 2p, 2p+1): D[16x16] over K=96, cached A fragments.
// ---------------------------------------------------------------------------
__device__ __forceinline__ void hmma_pair(const uint32_t af[6][4], uint32_t wAddr,
                                          int p, float acc[2][4])
{
#pragma unroll
    for (int t = 0; t < 2; t++)
#pragma unroll
        for (int r = 0; r < 4; r++) acc[t][r] = 0.f;
#pragma unroll
    for (int ks = 0; ks < 6; ks++) {
        uint32_t b0, b1, b2, b3;
        ldsm4(b0, b1, b2, b3, wAddr + p * 3328 + ks * 32);
        MMA(acc[0], af[ks], b0, b2);
        MMA(acc[1], af[ks], b1, b3);
    }
}

// stage one 96x104-bf16 weight image (19968B = 1248 x 16B) via cp.async
__device__ __forceinline__ void stage_w_async(uint32_t dst, const char* src, int tid)
{
    for (int f = tid; f < 1248; f += 256)
        CPA16(dst + f * 16, src + f * 16);
}

// ---------------------------------------------------------------------------
// Side blocks (bid >= 256): W' fold (18), b' (1), projs_w transpose (3).
// ---------------------------------------------------------------------------
__device__ void side_block(char* smem, int bid, int tid,
                           const float* pr, const float* sw,
                           const float* swb, const float* prb,
                           const float* prs_ext)
{
    float* prs  = (float*)smem;             // [96][100] fp32
    float* sws  = (float*)(smem + 38400);   // [16][96] fp32
    float* prbs = (float*)(smem + 44544);   // [96]

    if (bid < 274) {
        // ---- 16 rows of W' = sw @ pr ----
        int jf0 = (bid - 256) * 16;
        for (int i = tid; i < 2304; i += 256) {
            int t = i / 24, c4 = (i % 24) * 4;
            *(float4*)&prs[t * 100 + c4] = *(const float4*)&pr[t * 96 + c4];
        }
        for (int i = tid; i < 1536; i += 256)
            sws[i] = sw[jf0 * 96 + i];
        __syncthreads();

        int rgrp = tid >> 4, cgrp = tid & 15;
        int c0 = cgrp * 6;
        const float* swr = &sws[rgrp * 96];
        float acc[6];
#pragma unroll
        for (int j = 0; j < 6; j++) acc[j] = 0.f;
#pragma unroll 4
        for (int t = 0; t < 96; t++) {
            float s = swr[t];
#pragma unroll
            for (int j = 0; j < 6; j++)
                acc[j] = fmaf(s, prs[t * 100 + c0 + j], acc[j]);
        }
        int jf = jf0 + rgrp;
#pragma unroll
        for (int j = 0; j < 6; j++)
            g_wbf[1][jf * 104 + c0 + j] = __float2bfloat16(acc[j]);
    } else if (bid == 274) {
        // ---- b' = sw @ prb + swb ----
        if (tid < 96) prbs[tid] = prb[tid];
        __syncthreads();
        int rgrp = tid >> 4, cgrp = tid & 15;
        int c0 = cgrp * 6;
        for (int r = rgrp; r < 288; r += 16) {
            const float* swr = sw + r * 96;
            float pacc = 0.f;
#pragma unroll
            for (int t = 0; t < 6; t++)
                pacc = fmaf(swr[c0 + t], prbs[c0 + t], pacc);
#pragma unroll
            for (int off = 1; off < 16; off <<= 1)
                pacc += __shfl_xor_sync(0xffffffffu, pacc, off);
            if (cgrp == 0) g_b1[r] = pacc + swb[r];
        }
    } else {
        // ---- projs_w transpose: 3 blocks x 3072 elems ----
        int base = (bid - 275) * 3072;
#pragma unroll
        for (int k = 0; k < 12; k++) {
            int idx = base + k * 256 + tid;   // < 9216
            int j = idx / 96, c = idx % 96;
            g_wpbf[j * 104 + c] = __float2bfloat16(prs_ext[idx]);
        }
    }
    __threadfence();
    __syncthreads();
    if (tid == 0) atomicAdd(&g_fold, 1);
}

// ---------------------------------------------------------------------------
// One branch phase (R12 fused body). BR=0: x -> o0 (g_mid). BR=1: o0 -> out.
// ---------------------------------------------------------------------------
template <int BR>
__device__ __forceinline__ void run_phase(char* smem, uint32_t sb,
                                          const float* __restrict__ xin_ext,
                                          const float* __restrict__ QB,
                                          const float* __restrict__ pr_b,
                                          float* __restrict__ out_ext,
                                          int shift, int bid)
{
    int*   tb = (int*)smem;
    float* qb = (float*)(smem + 512);
    float* pb = (float*)(smem + 1664);
    float* gt = (float*)(smem + 2048);
    float* gc = (float*)(smem + 4096);
    char*  smA = smem + 5120;
    uint32_t smAu = sb + 5120;
    uint32_t smWu = sb + 31744;             // 3 x [96][104] bf16 slots

    int tid = threadIdx.x, w = tid >> 5, lane = tid & 31;
    int g = lane >> 2, tig = lane & 3;
    int l16 = lane & 15, lh = lane >> 4;
    int row0 = w * 16;

    for (int i = tid; i < 288; i += 256) qb[i] = QB[i];
    if (BR && tid < 96) pb[tid] = pr_b[tid];

    if (tid < 128) {
        int pi = tid & 63;
        int gg = (bid << 6) + pi;
        int b = gg >> 13, dw = (gg >> 10) & 7, p = gg & 1023;
        int d = (2 * dw + (tid >> 6) + shift) & 15;
        tb[tid] = ((b * 16 + d) * 1024 + p) * 96;
    }

    const char* WB = (const char*)g_wbf[BR];

    if (BR == 0) {
        stage_w_async(smWu,             WB + 96 * 208, tid);   // K
        stage_w_async(smWu + 19968,     WB + 192 * 208, tid);  // V
        stage_w_async(smWu + 2 * 19968, WB,             tid);  // Q
        CPA_COMMIT();
        __syncthreads();   // tb ready
        for (int f4 = tid; f4 < 3072; f4 += 256) {
            int l = f4 / 24, q4 = f4 % 24;
            float4 v = *(const float4*)&xin_ext[tb[l] + q4 * 4];
            __nv_bfloat162 p0 = __floats2bfloat162_rn(v.x, v.y);
            __nv_bfloat162 p1 = __floats2bfloat162_rn(v.z, v.w);
            *(uint2*)(smA + l * 208 + q4 * 8) =
                make_uint2(*(uint32_t*)&p0, *(uint32_t*)&p1);
        }
    } else {
        __syncthreads();   // tb ready
        for (int f = tid; f < 1536; f += 256) {       // A tile via cp.async (L2)
            int l = f / 12, u = f % 12;
            CPA16(smAu + l * 208 + u * 16,
                  (const char*)g_mid + (size_t)tb[l] * 2 + u * 16);
        }
        stage_w_async(smWu,             WB + 96 * 208, tid);   // K'
        stage_w_async(smWu + 19968,     WB + 192 * 208, tid);  // V'
        stage_w_async(smWu + 2 * 19968, WB,             tid);  // Q'
        CPA_COMMIT();
    }

    uint32_t aAddr = smAu + ((row0 + l16) * 104 + lh * 8) * 2;
    uint32_t wAddr = smWu + (l16 * 104 + lh * 8) * 2;

    CPA_WAIT(0);
    __syncthreads();        // A + K + V + Q visible

    uint32_t af[6][4];
#pragma unroll
    for (int ks = 0; ks < 6; ks++)
        ldsm4(af[ks][0], af[ks][1], af[ks][2], af[ks][3], aAddr + ks * 32);

    // ---- mega loop: K, V, Q per pair; K/V fold into G; Q held in regs ----
    float G[8];
    float qacc[6][2][4];
#pragma unroll
    for (int i = 0; i < 8; i++) G[i] = 0.f;
#pragma unroll
    for (int p = 0; p < 6; p++) {
        float ka[2][4], va[2][4];
        hmma_pair(af, wAddr,             p, ka);
        hmma_pair(af, wAddr + 19968,     p, va);
        hmma_pair(af, wAddr + 2 * 19968, p, qacc[p]);
#pragma unroll
        for (int t = 0; t < 2; t++) {
            int j0 = (2 * p + t) * 8 + tig * 2;
            float kb0 = qb[96 + j0], kb1 = qb[96 + j0 + 1];
            float vb0 = qb[192 + j0], vb1 = qb[192 + j0 + 1];
            float k0 = ka[t][0] + kb0, k1 = ka[t][1] + kb1;
            float k2 = ka[t][2] + kb0, k3 = ka[t][3] + kb1;
            float v0 = va[t][0] + vb0, v1 = va[t][1] + vb1;
            float v2 = va[t][2] + vb0, v3 = va[t][3] + vb1;
            G[0] = fmaf(k0, v0, G[0]); G[1] = fmaf(k0, v1, G[1]);
            G[2] = fmaf(k1, v0, G[2]); G[3] = fmaf(k1, v1, G[3]);
            G[4] = fmaf(k2, v2, G[4]); G[5] = fmaf(k2, v3, G[5]);
            G[6] = fmaf(k3, v2, G[6]); G[7] = fmaf(k3, v3, G[7]);
        }
    }
    __syncthreads();        // all warps done reading weight slots

    if (BR) { stage_w_async(smWu, (const char*)g_wpbf, tid); CPA_COMMIT(); }

#pragma unroll
    for (int off = 1; off <= 2; off <<= 1)
#pragma unroll
        for (int i = 0; i < 8; i++)
            G[i] += __shfl_xor_sync(0xffffffffu, G[i], off);
    if (tig == 0) {
        *(float4*)&gt[(row0 + g) * 4]     = make_float4(G[0], G[1], G[2], G[3]);
        *(float4*)&gt[(row0 + g + 8) * 4] = make_float4(G[4], G[5], G[6], G[7]);
    }
    __syncthreads();
    if (tid < 64) {
        float4 a = *(float4*)&gt[tid * 4];
        float4 b4 = *(float4*)&gt[(tid + 64) * 4];
        *(float4*)&gc[tid * 4] =
            make_float4(a.x + b4.x, a.y + b4.y, a.z + b4.z, a.w + b4.w);
    }
    CPA_WAIT(0);
    __syncthreads();        // gc (+ proj weights) visible

    float4 Glo = *(float4*)&gc[((row0 + g) & 63) * 4];
    float4 Ghi = *(float4*)&gc[((row0 + g + 8) & 63) * 4];

#pragma unroll
    for (int p = 0; p < 6; p++) {
#pragma unroll
        for (int t = 0; t < 2; t++) {
            int j0 = (2 * p + t) * 8 + tig * 2;
            float b0 = qb[j0], b1 = qb[j0 + 1];
            float q0 = qacc[p][t][0] + b0, q1 = qacc[p][t][1] + b1;
            float q2 = qacc[p][t][2] + b0, q3 = qacc[p][t][3] + b1;
            float o0 = q0 * Glo.x + q1 * Glo.z;
            float o1 = q0 * Glo.y + q1 * Glo.w;
            float o2 = q2 * Ghi.x + q3 * Ghi.z;
            float o3 = q2 * Ghi.y + q3 * Ghi.w;
            __nv_bfloat162 plo = __floats2bfloat162_rn(o0, o1);
            __nv_bfloat162 phi = __floats2bfloat162_rn(o2, o3);
            *(uint32_t*)(smA + (row0 + g) * 208 + j0 * 2)     = *(uint32_t*)&plo;
            *(uint32_t*)(smA + (row0 + g + 8) * 208 + j0 * 2) = *(uint32_t*)&phi;
        }
    }

    if (BR == 0) {
        __syncthreads();
        for (int f = tid; f < 1536; f += 256) {
            int l = f / 12, u = f % 12;
            *(uint4*)((char*)g_mid + (size_t)tb[l] * 2 + u * 16) =
                *(const uint4*)(smA + l * 208 + u * 16);
        }
    } else {
        __syncwarp();       // order own-warp STS -> LDSM
        uint32_t of[6][4];
#pragma unroll
        for (int ks = 0; ks < 6; ks++)
            ldsm4(of[ks][0], of[ks][1], of[ks][2], of[ks][3], aAddr + ks * 32);
        int tbg = tb[row0 + g], tbh = tb[row0 + g + 8];
#pragma unroll
        for (int p = 0; p < 6; p++) {
            float pa[2][4];
            hmma_pair(of, wAddr, p, pa);     // slot0 = proj weights
#pragma unroll
            for (int t = 0; t < 2; t++) {
                int j0 = (2 * p + t) * 8 + tig * 2;
                float b0 = pb[j0], b1 = pb[j0 + 1];
                *(float2*)&out_ext[tbg + j0] =
                    make_float2(pa[t][0] + b0, pa[t][1] + b1);
                *(float2*)&out_ext[tbh + j0] =
                    make_float2(pa[t][2] + b0, pa[t][3] + b1);
            }
        }
    }
}

// ---------------------------------------------------------------------------
// Mega kernel. Grid 278 x 256 (256 work + 22 side), all resident in wave 1.
// ---------------------------------------------------------------------------
__global__ void __launch_bounds__(256, 2)
fused_mega(const float* __restrict__ x,
           const float* __restrict__ lr_b,
           const float* __restrict__ projs_b,
           float* __restrict__ out,
           const float* __restrict__ f_pr,    // proj_w
           const float* __restrict__ f_sw,    // sw_w
           const float* __restrict__ f_swb,   // sw_b
           const float* __restrict__ f_prb,   // proj_b
           const float* __restrict__ f_prs)   // projs_w
{
    extern __shared__ char smem[];
    int tid = threadIdx.x, bid = blockIdx.x;

    if (bid >= 256) {
        side_block(smem, bid, tid, f_pr, f_sw, f_swb, f_prb, f_prs);
        return;
    }

    uint32_t sb = smem_u32(smem);

    // ---- phase A: branch 0, pairs (2w, 2w+1), x -> o0 ----
    run_phase<0>(smem, sb, x, lr_b, nullptr, nullptr, 0, bid);

    __threadfence();
    __syncthreads();
    if (tid == 0) atomicExch(&g_flag[bid], 1);

    // ---- wait: own dw-1 neighbor's phase A + side blocks ----
    if (tid == 0) {
        int dw = (bid >> 4) & 7;
        int dep = (bid & 0x8F) | (((dw + 7) & 7) << 4);
        while (*(volatile int*)&g_fold < 22) {}
        while (*(volatile int*)&g_flag[dep] == 0) {}
    }
    __syncthreads();
    __threadfence();

    // ---- phase B: branch 1, pairs (2w-1, 2w), o0 -> out ----
    run_phase<1>(smem, sb, nullptr, g_b1, projs_b, out, 15, bid);
}

// ---------------------------------------------------------------------------
extern "C" void kernel_launch(void* const* d_in, const int* in_sizes, int n_in,
                              void* d_out, int out_size)
{
    const float* x       = (const float*)d_in[0];
    const float* lr_w    = (const float*)d_in[1];
    const float* lr_b    = (const float*)d_in[2];
    const float* proj_w  = (const float*)d_in[3];
    const float* proj_b  = (const float*)d_in[4];
    const float* sw_w    = (const float*)d_in[5];
    const float* sw_b    = (const float*)d_in[6];
    const float* projs_w = (const float*)d_in[7];
    const float* projs_b = (const float*)d_in[8];
    float* out = (float*)d_out;

    cudaFuncSetAttribute(fused_mega,
                         cudaFuncAttributeMaxDynamicSharedMemorySize, SMEM_BYTES);

    prep_tr<<<108, 256>>>(lr_w);   // lr transpose + flag/counter reset
    fused_mega<<<278, 256, SMEM_BYTES>>>(x, lr_b, projs_b, out,
                                         proj_w, sw_w, sw_b, proj_b, projs_w);
}